// round 1
// baseline (speedup 1.0000x reference)
#include <cuda_runtime.h>

// DepthLoss3D: N=4096 (16x16x16), 3 channels.
// out[c] = sum_{i,j} f(p[i,c]-p[j,c], s_i[c]-s_j[c]) / N^2
// where s_e[c] = float(coord_c(e)) * spacing[c] * 2   (matches reference rounding order)
// f(x, ds): t = (x>=0) ? x - 0.2*ds : x
//           t = (t>=0) ? max(t - 0.8*ds, 0) : t
//           w = ds>0 ? 1 : (ds==0 ? 0.5 : 0)
//           f = w * |t|

#define N_ELEM 4096
#define TILE   128

__global__ void __launch_bounds__(TILE) depthloss3d_kernel(
    const float* __restrict__ pred,   // [N,3]
    const float* __restrict__ spac,   // [3]
    float* __restrict__ out)          // [3]
{
    __shared__ float4 sh_a[TILE];   // {p0, p1, p2, s0}
    __shared__ float2 sh_b[TILE];   // {s1, s2}
    __shared__ float  red[4][3];

    const int tid   = threadIdx.x;
    const int i     = blockIdx.x * TILE + tid;
    const int jbase = blockIdx.y * TILE;

    const float k0 = spac[0] * 2.0f;
    const float k1 = spac[1] * 2.0f;
    const float k2 = spac[2] * 2.0f;

    // Stage the j-tile into shared memory.
    {
        const int j = jbase + tid;
        const float p0 = pred[j * 3 + 0];
        const float p1 = pred[j * 3 + 1];
        const float p2 = pred[j * 3 + 2];
        const float s0 = (float)(j >> 8)        * k0;
        const float s1 = (float)((j >> 4) & 15) * k1;
        const float s2 = (float)(j & 15)        * k2;
        sh_a[tid] = make_float4(p0, p1, p2, s0);
        sh_b[tid] = make_float2(s1, s2);
    }
    __syncthreads();

    const float pi0 = pred[i * 3 + 0];
    const float pi1 = pred[i * 3 + 1];
    const float pi2 = pred[i * 3 + 2];
    const float si0 = (float)(i >> 8)        * k0;
    const float si1 = (float)((i >> 4) & 15) * k1;
    const float si2 = (float)(i & 15)        * k2;

    float acc0 = 0.0f, acc1 = 0.0f, acc2 = 0.0f;

#pragma unroll 8
    for (int jj = 0; jj < TILE; ++jj) {
        const float4 a = sh_a[jj];
        const float2 b = sh_b[jj];

        // channel 0
        {
            const float ds = si0 - a.w;
            const float x  = pi0 - a.x;
            float t = (x >= 0.0f) ? (x - 0.2f * ds) : x;
            t = (t >= 0.0f) ? fmaxf(t - 0.8f * ds, 0.0f) : t;
            const float w = (ds > 0.0f) ? 1.0f : ((ds == 0.0f) ? 0.5f : 0.0f);
            acc0 = fmaf(w, fabsf(t), acc0);
        }
        // channel 1
        {
            const float ds = si1 - b.x;
            const float x  = pi1 - a.y;
            float t = (x >= 0.0f) ? (x - 0.2f * ds) : x;
            t = (t >= 0.0f) ? fmaxf(t - 0.8f * ds, 0.0f) : t;
            const float w = (ds > 0.0f) ? 1.0f : ((ds == 0.0f) ? 0.5f : 0.0f);
            acc1 = fmaf(w, fabsf(t), acc1);
        }
        // channel 2
        {
            const float ds = si2 - b.y;
            const float x  = pi2 - a.z;
            float t = (x >= 0.0f) ? (x - 0.2f * ds) : x;
            t = (t >= 0.0f) ? fmaxf(t - 0.8f * ds, 0.0f) : t;
            const float w = (ds > 0.0f) ? 1.0f : ((ds == 0.0f) ? 0.5f : 0.0f);
            acc2 = fmaf(w, fabsf(t), acc2);
        }
    }

    // Warp reduction.
#pragma unroll
    for (int off = 16; off > 0; off >>= 1) {
        acc0 += __shfl_xor_sync(0xffffffffu, acc0, off);
        acc1 += __shfl_xor_sync(0xffffffffu, acc1, off);
        acc2 += __shfl_xor_sync(0xffffffffu, acc2, off);
    }
    if ((tid & 31) == 0) {
        red[tid >> 5][0] = acc0;
        red[tid >> 5][1] = acc1;
        red[tid >> 5][2] = acc2;
    }
    __syncthreads();

    if (tid == 0) {
        const float inv = 1.0f / ((float)N_ELEM * (float)N_ELEM);
        float t0 = red[0][0] + red[1][0] + red[2][0] + red[3][0];
        float t1 = red[0][1] + red[1][1] + red[2][1] + red[3][1];
        float t2 = red[0][2] + red[1][2] + red[2][2] + red[3][2];
        atomicAdd(&out[0], t0 * inv);
        atomicAdd(&out[1], t1 * inv);
        atomicAdd(&out[2], t2 * inv);
    }
}

extern "C" void kernel_launch(void* const* d_in, const int* in_sizes, int n_in,
                              void* d_out, int out_size)
{
    (void)in_sizes; (void)n_in; (void)out_size;
    const float* pred = (const float*)d_in[0];
    const float* spac = (const float*)d_in[1];
    float* out = (float*)d_out;

    cudaMemsetAsync(out, 0, 3 * sizeof(float));

    dim3 grid(N_ELEM / TILE, N_ELEM / TILE);  // 32 x 32 = 1024 blocks
    depthloss3d_kernel<<<grid, TILE>>>(pred, spac, out);
}

// round 2
// speedup vs baseline: 2.3472x; 2.3472x over previous
#include <cuda_runtime.h>

// DepthLoss3D, grouped-by-coordinate formulation.
// For channel c, group points by grid coordinate (16 groups of 256).
// ds = (a-b)*k, k = spacing[c]*2 > 0:
//   a <  b : weight 0 -> skipped (not launched)
//   a == b : f = 0.5*|pi - pj|
//   a >  b : f = (x<0) ? -x : max(x-ds, max(0.2ds - x, 0)),  x = pi - pj
// out[c] = sum f / N^2

#define N_ELEM 4096

__global__ void __launch_bounds__(256) depthloss_grouped(
    const float* __restrict__ pred,   // [4096,3]
    const float* __restrict__ spac,   // [3]
    float* __restrict__ out)          // [3]
{
    __shared__ float sb[128];
    __shared__ float red[8];

    const int bx    = blockIdx.x;
    const int task  = bx >> 1;        // 0..407
    const int jhalf = bx & 1;
    const int c     = task / 136;
    const int pq    = task - c * 136; // triangular index, 0..135

    // decode (a,b) with a >= b from triangular index
    int a = (int)((sqrtf(8.0f * (float)pq + 1.0f) - 1.0f) * 0.5f);
    while ((a + 1) * (a + 2) / 2 <= pq) ++a;
    while (a * (a + 1) / 2 > pq) --a;
    const int b = pq - a * (a + 1) / 2;

    const int t = threadIdx.x;

    const float k   = spac[c] * 2.0f;
    const float ds  = (float)a * k - (float)b * k;  // match reference rounding order
    const float c1  = 0.2f * ds;

    // global linear index of element m (0..255) of group g for channel c
    // c=0: h=g         -> i = g*256 + m
    // c=1: w=g         -> i = (m>>4)*256 + g*16 + (m&15)
    // c=2: d=g         -> i = m*16 + g
    int ji;
    {
        const int n = (jhalf << 7) + (t & 127);
        if (c == 0)      ji = (b << 8) + n;
        else if (c == 1) ji = ((n >> 4) << 8) + (b << 4) + (n & 15);
        else             ji = (n << 4) + b;
    }
    if (t < 128) sb[t] = pred[ji * 3 + c];

    int ii;
    if (c == 0)      ii = (a << 8) + t;
    else if (c == 1) ii = ((t >> 4) << 8) + (a << 4) + (t & 15);
    else             ii = (t << 4) + a;

    __syncthreads();

    const float p = pred[ii * 3 + c];
    float acc = 0.0f;

    const float4* s4 = (const float4*)sb;

    if (a == b) {
#pragma unroll 8
        for (int q = 0; q < 32; ++q) {
            const float4 vv = s4[q];
            acc += fabsf(p - vv.x);
            acc += fabsf(p - vv.y);
            acc += fabsf(p - vv.z);
            acc += fabsf(p - vv.w);
        }
        acc *= 0.5f;
    } else {
        const float v  = p - ds;   // x - ds  = v  - pb
        const float w2 = p - c1;   // c1 - x  = pb - w2
#pragma unroll 8
        for (int q = 0; q < 32; ++q) {
            const float4 vv = s4[q];
            {
                const float pb = vv.x;
                const float C  = pb - p;                          // -x
                const float m2 = fmaxf(v - pb, fmaxf(pb - w2, 0.0f));
                acc += (C > 0.0f) ? C : m2;
            }
            {
                const float pb = vv.y;
                const float C  = pb - p;
                const float m2 = fmaxf(v - pb, fmaxf(pb - w2, 0.0f));
                acc += (C > 0.0f) ? C : m2;
            }
            {
                const float pb = vv.z;
                const float C  = pb - p;
                const float m2 = fmaxf(v - pb, fmaxf(pb - w2, 0.0f));
                acc += (C > 0.0f) ? C : m2;
            }
            {
                const float pb = vv.w;
                const float C  = pb - p;
                const float m2 = fmaxf(v - pb, fmaxf(pb - w2, 0.0f));
                acc += (C > 0.0f) ? C : m2;
            }
        }
    }

    // block reduction
#pragma unroll
    for (int off = 16; off > 0; off >>= 1)
        acc += __shfl_xor_sync(0xffffffffu, acc, off);
    if ((t & 31) == 0) red[t >> 5] = acc;
    __syncthreads();

    if (t == 0) {
        float tot = red[0] + red[1] + red[2] + red[3]
                  + red[4] + red[5] + red[6] + red[7];
        const float inv = 1.0f / ((float)N_ELEM * (float)N_ELEM);
        atomicAdd(&out[c], tot * inv);
    }
}

extern "C" void kernel_launch(void* const* d_in, const int* in_sizes, int n_in,
                              void* d_out, int out_size)
{
    (void)in_sizes; (void)n_in; (void)out_size;
    const float* pred = (const float*)d_in[0];
    const float* spac = (const float*)d_in[1];
    float* out = (float*)d_out;

    cudaMemsetAsync(out, 0, 3 * sizeof(float));

    // 3 channels * 136 (a>=b) pairs * 2 j-halves
    depthloss_grouped<<<816, 256>>>(pred, spac, out);
}

// round 3
// speedup vs baseline: 2.3532x; 1.0026x over previous
#include <cuda_runtime.h>

// DepthLoss3D via sorted-group closed form.
// Points grouped per channel by grid coordinate (16 groups x 256).
// ds = a*k - b*k, k = spacing[c]*2 > 0. Pairs a<b have weight 0.
// a==b: contribution = sum_r v_(r) * (2r-255)            (sorted ascending)
// a> b: per i: f-sum over sorted group B via 3 binary searches + prefix sums:
//   f(x) = max(x-ds, 0.2ds-x, 0) - 0.2ds*[x<0],  x = p - pb
//   sum_j f = n1*k1 - P[n1] + (T - P[n2]) - (256-n2)*k2 - 0.2ds*(256-n3)
//   k1 = p-ds (strict <), k2 = p-0.2ds (<=), n3 = count(pb <= p)

#define N_ELEM 4096

__device__ float g_sorted[3][16][256];
__device__ float g_prefix[3][16][257];

__device__ __forceinline__ int elem_index(int c, int g, int m) {
    if (c == 0)      return (g << 8) + m;
    else if (c == 1) return ((m >> 4) << 8) + (g << 4) + (m & 15);
    else             return (m << 4) + g;
}

// 48 blocks: (c,g). Sort group, prefix-scan, store, add diagonal term.
__global__ void __launch_bounds__(256) sort_kernel(
    const float* __restrict__ pred,
    float* __restrict__ out)
{
    __shared__ float s[256];
    __shared__ float ps[256];
    __shared__ float red[8];
    const int t = threadIdx.x;
    const int c = blockIdx.x >> 4;
    const int g = blockIdx.x & 15;

    const int i = elem_index(c, g, t);
    s[t] = pred[i * 3 + c];
    __syncthreads();

    // Bitonic sort, ascending.
    for (int k = 2; k <= 256; k <<= 1) {
        for (int j = k >> 1; j > 0; j >>= 1) {
            const int ixj = t ^ j;
            if (ixj > t) {
                const float av = s[t], bv = s[ixj];
                const bool up = ((t & k) == 0);
                if ((av > bv) == up) { s[t] = bv; s[ixj] = av; }
            }
            __syncthreads();
        }
    }

    const float val = s[t];

    // Inclusive scan (Hillis-Steele).
    ps[t] = val;
    __syncthreads();
    for (int off = 1; off < 256; off <<= 1) {
        const float add = (t >= off) ? ps[t - off] : 0.0f;
        __syncthreads();
        ps[t] += add;
        __syncthreads();
    }

    g_sorted[c][g][t]     = val;
    g_prefix[c][g][t + 1] = ps[t];
    if (t == 0) g_prefix[c][g][0] = 0.0f;

    // Diagonal (a==b) contribution: 0.5 * sum_{i,j} |vi-vj| = sum_r v_(r)(2r-255)
    float w = val * (float)(2 * t - 255);
#pragma unroll
    for (int off = 16; off > 0; off >>= 1)
        w += __shfl_xor_sync(0xffffffffu, w, off);
    if ((t & 31) == 0) red[t >> 5] = w;
    __syncthreads();
    if (t == 0) {
        float tot = red[0] + red[1] + red[2] + red[3]
                  + red[4] + red[5] + red[6] + red[7];
        atomicAdd(&out[c], tot * (1.0f / ((float)N_ELEM * (float)N_ELEM)));
    }
}

// 360 blocks: (c, strict pair a>b). One i per thread, closed form over B.
__global__ void __launch_bounds__(256) pair_kernel(
    const float* __restrict__ spac,
    float* __restrict__ out)
{
    __shared__ float sv[256];
    __shared__ float sp[257];
    __shared__ float red[8];
    const int t  = threadIdx.x;
    const int bx = blockIdx.x;
    const int c  = bx / 120;
    const int pq = bx - c * 120;

    // decode a>b from pq = a*(a-1)/2 + b
    int a = 1;
    while ((a + 1) * a / 2 <= pq) ++a;
    const int b = pq - a * (a - 1) / 2;

    sv[t] = g_sorted[c][b][t];
    sp[t] = g_prefix[c][b][t];
    if (t == 0) sp[256] = g_prefix[c][b][256];
    __syncthreads();

    const float k  = spac[c] * 2.0f;
    const float ds = (float)a * k - (float)b * k;
    const float c1 = 0.2f * ds;
    const float p  = g_sorted[c][a][t];
    const float k1 = p - ds;
    const float k2 = p - c1;

    // Branchless counting searches over sorted sv (n=256).
    int cnt1 = 0, cnt2 = 0, cnt3 = 0;
#pragma unroll
    for (int s = 128; s > 0; s >>= 1) {
        cnt1 += (sv[cnt1 + s - 1] <  k1) ? s : 0;
        cnt2 += (sv[cnt2 + s - 1] <= k2) ? s : 0;
        cnt3 += (sv[cnt3 + s - 1] <= p ) ? s : 0;
    }
    cnt1 += (sv[cnt1] <  k1) ? 1 : 0;
    cnt2 += (sv[cnt2] <= k2) ? 1 : 0;
    cnt3 += (sv[cnt3] <= p ) ? 1 : 0;

    const float T = sp[256];
    float contrib = (float)cnt1 * k1 - sp[cnt1]          // sum of (x-ds) over t1>0
                  + (T - sp[cnt2]) - (float)(256 - cnt2) * k2  // sum of (0.2ds-x) over t2>0
                  - c1 * (float)(256 - cnt3);            // -0.2ds * #{x<0}

#pragma unroll
    for (int off = 16; off > 0; off >>= 1)
        contrib += __shfl_xor_sync(0xffffffffu, contrib, off);
    if ((t & 31) == 0) red[t >> 5] = contrib;
    __syncthreads();
    if (t == 0) {
        float tot = red[0] + red[1] + red[2] + red[3]
                  + red[4] + red[5] + red[6] + red[7];
        atomicAdd(&out[c], tot * (1.0f / ((float)N_ELEM * (float)N_ELEM)));
    }
}

extern "C" void kernel_launch(void* const* d_in, const int* in_sizes, int n_in,
                              void* d_out, int out_size)
{
    (void)in_sizes; (void)n_in; (void)out_size;
    const float* pred = (const float*)d_in[0];
    const float* spac = (const float*)d_in[1];
    float* out = (float*)d_out;

    cudaMemsetAsync(out, 0, 3 * sizeof(float));
    sort_kernel<<<48, 256>>>(pred, out);
    pair_kernel<<<360, 256>>>(spac, out);
}

// round 4
// speedup vs baseline: 2.8491x; 1.2107x over previous
#include <cuda_runtime.h>

// DepthLoss3D, single fused kernel.
// Per channel c, group the 4096 points by grid coordinate (16 groups x 256).
// ds = a*k - b*k, k = spacing[c]*2 > 0. Pairs a<b contribute 0.
// Diagonal (a==b): 0.5 * sum|vi-vj| = sum_r v_(r)*(2r-255) over sorted values.
// Pair (a>b), per i with x = p - pb:
//   f(x) = max(x-ds, 0.2ds-x, 0) - 0.2ds*[x<0]
//   sum over sorted B via prefix sums + 3 binary searches:
//   n1*k1 - P[n1] + (T - P[n2]) - (256-n2)*k2 - 0.2ds*(256-n3)
//   k1 = p-ds (strict <), k2 = p-0.2ds (<=), n3 = count(pb <= p)
// Each block sorts its own B group -> no inter-kernel dependency.

#define N_ELEM 4096

__device__ __forceinline__ int elem_index(int c, int g, int m) {
    if (c == 0)      return (g << 8) + m;
    else if (c == 1) return ((m >> 4) << 8) + (g << 4) + (m & 15);
    else             return (m << 4) + g;
}

__global__ void __launch_bounds__(256) depthloss_fused(
    const float* __restrict__ pred,   // [4096,3]
    const float* __restrict__ spac,   // [3]
    float* __restrict__ out)          // [3]
{
    __shared__ float sv[256];
    __shared__ float sp[257];
    __shared__ float red[8];

    const int t    = threadIdx.x;
    const int lane = t & 31;
    const int wid  = t >> 5;
    const int bx   = blockIdx.x;

    // Task decode: bx < 48 -> diagonal (c,g); else pair (c, a>b).
    int c, a, b;
    bool diag;
    if (bx < 48) {
        diag = true;
        c = bx >> 4;
        a = b = bx & 15;
    } else {
        diag = false;
        const int idx = bx - 48;
        c = idx / 120;
        const int pq = idx - c * 120;
        a = 1;
        while ((a + 1) * a / 2 <= pq) ++a;
        b = pq - a * (a - 1) / 2;
    }

    // Load group-b element (to be sorted) and, for pairs, the raw p from group a.
    float v = pred[elem_index(c, b, t) * 3 + c];
    float p = diag ? 0.0f : pred[elem_index(c, a, t) * 3 + c];

    // ---- Bitonic sort of v across the block (ascending by rank t). ----
    // Stages with j<=16: warp shuffles (no barriers). j>=32: via shared.
#pragma unroll
    for (int k = 2; k <= 256; k <<= 1) {
        const bool up = ((t & k) == 0);
        int j = k >> 1;
        for (; j >= 32; j >>= 1) {
            sv[t] = v;
            __syncthreads();
            const float other = sv[t ^ j];
            const bool keepMin = (((t & j) == 0) == up);
            v = keepMin ? fminf(v, other) : fmaxf(v, other);
            __syncthreads();
        }
#pragma unroll
        for (; j >= 1; j >>= 1) {
            const float other = __shfl_xor_sync(0xffffffffu, v, j);
            const bool keepMin = (((t & j) == 0) == up);
            v = keepMin ? fminf(v, other) : fmaxf(v, other);
        }
    }

    const float inv = 1.0f / ((float)N_ELEM * (float)N_ELEM);

    if (diag) {
        // sum_r v_(r) * (2r - 255)
        float w = v * (float)(2 * t - 255);
#pragma unroll
        for (int off = 16; off > 0; off >>= 1)
            w += __shfl_xor_sync(0xffffffffu, w, off);
        if (lane == 0) red[wid] = w;
        __syncthreads();
        if (t == 0) {
            float tot = red[0] + red[1] + red[2] + red[3]
                      + red[4] + red[5] + red[6] + red[7];
            atomicAdd(&out[c], tot * inv);
        }
        return;
    }

    // ---- Inclusive prefix scan of sorted v. ----
    float x = v;
#pragma unroll
    for (int off = 1; off < 32; off <<= 1) {
        const float y = __shfl_up_sync(0xffffffffu, x, off);
        if (lane >= off) x += y;
    }
    if (lane == 31) red[wid] = x;   // per-warp totals
    __syncthreads();
    float woff = 0.0f;
#pragma unroll
    for (int w = 0; w < 8; ++w)
        woff += (w < wid) ? red[w] : 0.0f;
    const float incl = x + woff;

    sv[t]     = v;
    sp[t + 1] = incl;
    if (t == 0) sp[0] = 0.0f;
    __syncthreads();

    // ---- Closed form. ----
    const float k  = spac[c] * 2.0f;
    const float ds = (float)a * k - (float)b * k;   // reference rounding order
    const float c1 = 0.2f * ds;
    const float k1 = p - ds;
    const float k2 = p - c1;

    int cnt1 = 0, cnt2 = 0, cnt3 = 0;
#pragma unroll
    for (int s = 128; s > 0; s >>= 1) {
        cnt1 += (sv[cnt1 + s - 1] <  k1) ? s : 0;
        cnt2 += (sv[cnt2 + s - 1] <= k2) ? s : 0;
        cnt3 += (sv[cnt3 + s - 1] <= p ) ? s : 0;
    }
    cnt1 += (sv[cnt1] <  k1) ? 1 : 0;
    cnt2 += (sv[cnt2] <= k2) ? 1 : 0;
    cnt3 += (sv[cnt3] <= p ) ? 1 : 0;

    const float T = sp[256];
    float contrib = (float)cnt1 * k1 - sp[cnt1]
                  + (T - sp[cnt2]) - (float)(256 - cnt2) * k2
                  - c1 * (float)(256 - cnt3);

#pragma unroll
    for (int off = 16; off > 0; off >>= 1)
        contrib += __shfl_xor_sync(0xffffffffu, contrib, off);
    __syncthreads();              // red[] reuse after scan
    if (lane == 0) red[wid] = contrib;
    __syncthreads();
    if (t == 0) {
        float tot = red[0] + red[1] + red[2] + red[3]
                  + red[4] + red[5] + red[6] + red[7];
        atomicAdd(&out[c], tot * inv);
    }
}

extern "C" void kernel_launch(void* const* d_in, const int* in_sizes, int n_in,
                              void* d_out, int out_size)
{
    (void)in_sizes; (void)n_in; (void)out_size;
    const float* pred = (const float*)d_in[0];
    const float* spac = (const float*)d_in[1];
    float* out = (float*)d_out;

    cudaMemsetAsync(out, 0, 3 * sizeof(float));
    depthloss_fused<<<408, 256>>>(pred, spac, out);
}